// round 14
// baseline (speedup 1.0000x reference)
#include <cuda_runtime.h>

// Fixed shapes
#define KDIM   51
#define KP     52                // padded K (row 51 = ones, carries EPS exactly)
#define BDIM   256
#define CCOLS  24576             // 8192 points * 3
#define TCOLS  192               // columns per gram block (64 per d)
#define GBLKS  128               // gram blocks
#define QBLKS  32                // quad blocks
#define NTHR   288               // gram: 9 warps; 273 combos -> <=1 per thread
#define QTHR   768               // quad: 24 warps = 8 b x 3 d per block
#define COLS_D 64                // columns per d per block
#define CPAD   56                // padded k-extent (multiple of 4 for LDS.128)
#define NTILE  13                // 52/4 k-tiles
#define NPAIRT 91                // upper-tri tile pairs
#define NCOMBO 273               // 91 * 3 d
#define NV4    (KDIM * TCOLS / 4)  // 2448 float4 loads per block
#define NLOAD  9                   // ceil(2448 / 288)
#define GFLTS  (3 * KP * KP)       // 8112
#define NPOS4  (GFLTS / 4)         // 2028
#define EPSF   1e-6f
#define MULTF  0.0025f

// Device state. Zero-init at module load; quad_kernel's finisher resets
// g_G / g_out / g_ctr after use, so every graph replay starts clean.
__device__ __align__(16) float g_G[GFLTS];
__device__ float    g_out;
__device__ unsigned g_ctr;

typedef unsigned long long ull;

__device__ __forceinline__ ull pack2(float a, float b) {
    ull r; asm("mov.b64 %0, {%1, %2};" : "=l"(r) : "f"(a), "f"(b)); return r;
}
__device__ __forceinline__ void unpack2(ull v, float& a, float& b) {
    asm("mov.b64 {%0, %1}, %2;" : "=f"(a), "=f"(b) : "l"(v));
}
__device__ __forceinline__ void ffma2(ull& d, ull a, ull b) {
    asm("fma.rn.f32x2 %0, %1, %2, %0;" : "+l"(d) : "l"(a), "l"(b));
}

// =========================== Gram kernel ===========================
// grid = 128, block = 288. Identical to the round-8 champion phase 1.
__global__ void __launch_bounds__(NTHR, 1)
gram_kernel(const float* __restrict__ bs) {
    __shared__ __align__(16) float smem[3 * COLS_D * CPAD];  // 43008 B

    const int tid = threadIdx.x;
    const int blk = blockIdx.x;
    const int c0  = blk * TCOLS;

    // Front-batched loads: 9 independent LDG.128 per thread (MLP ~9).
    float4 vals[NLOAD];
    int    vv[NLOAD];
#pragma unroll
    for (int i = 0; i < NLOAD; i++) {
        int v = tid + i * NTHR;
        vv[i] = v;
        if (v < NV4) {
            int k = v / 48;            // 48 float4 per row
            int q = v - k * 48;
            vals[i] = *reinterpret_cast<const float4*>(
                bs + (size_t)k * CCOLS + c0 + q * 4);
        }
    }
    // De-interleave stores: c = q*4 + j; d = c%3, col = c/3.
#pragma unroll
    for (int i = 0; i < NLOAD; i++) {
        if (vv[i] < NV4) {
            int k  = vv[i] / 48;
            int q  = vv[i] - k * 48;
            int c  = q * 4;
            int q3 = c % 3;
            int qc = c / 3;
            float x[4] = {vals[i].x, vals[i].y, vals[i].z, vals[i].w};
#pragma unroll
            for (int j = 0; j < 4; j++) {
                int t   = q3 + j;              // 0..5
                int add = (t >= 3) ? 1 : 0;
                int d   = t - 3 * add;
                int col = qc + add;
                smem[(d * COLS_D + col) * CPAD + k] = x[j];
            }
        }
    }
    // Ones row (k = 51): carries EPS cross & square terms exactly.
    if (tid < TCOLS) {
        int d = tid % 3, col = tid / 3;
        smem[(d * COLS_D + col) * CPAD + KDIM] = 1.0f;
    }
    __syncthreads();

    // <=1 combo per thread, staggered across blocks (37 coprime to 273).
    if (tid < NCOMBO) {
        int combo = (tid + blk * 37) % NCOMBO;
        int d2   = combo / NPAIRT;
        int tile = combo - d2 * NPAIRT;
        int ti = 0, rem = tile;
        while (rem >= NTILE - ti) { rem -= NTILE - ti; ti++; }
        int tj = ti + rem;  // ti <= tj

        ull acc2[2][4];
#pragma unroll
        for (int p = 0; p < 2; p++)
#pragma unroll
            for (int s = 0; s < 4; s++) acc2[p][s] = 0ull;

        const float* base = smem + d2 * COLS_D * CPAD;
#pragma unroll 8
        for (int col2 = 0; col2 < COLS_D; col2++) {
            longlong2 a = *reinterpret_cast<const longlong2*>(
                base + col2 * CPAD + ti * 4);
            float4 b = *reinterpret_cast<const float4*>(
                base + col2 * CPAD + tj * 4);
            ull bx = pack2(b.x, b.x), by = pack2(b.y, b.y);
            ull bz = pack2(b.z, b.z), bw = pack2(b.w, b.w);
            ffma2(acc2[0][0], (ull)a.x, bx);
            ffma2(acc2[0][1], (ull)a.x, by);
            ffma2(acc2[0][2], (ull)a.x, bz);
            ffma2(acc2[0][3], (ull)a.x, bw);
            ffma2(acc2[1][0], (ull)a.y, bx);
            ffma2(acc2[1][1], (ull)a.y, by);
            ffma2(acc2[1][2], (ull)a.y, bz);
            ffma2(acc2[1][3], (ull)a.y, bw);
        }

#pragma unroll
        for (int p = 0; p < 2; p++) {
            float r0x, r1x, r0y, r1y, r0z, r1z, r0w, r1w;
            unpack2(acc2[p][0], r0x, r1x);
            unpack2(acc2[p][1], r0y, r1y);
            unpack2(acc2[p][2], r0z, r1z);
            unpack2(acc2[p][3], r0w, r1w);
            float4 v0 = make_float4(r0x, r0y, r0z, r0w);
            float4 v1 = make_float4(r1x, r1y, r1z, r1w);
            int r0 = ti * 4 + 2 * p;
            atomicAdd(reinterpret_cast<float4*>(
                          &g_G[d2 * KP * KP + r0 * KP + tj * 4]), v0);
            atomicAdd(reinterpret_cast<float4*>(
                          &g_G[d2 * KP * KP + (r0 + 1) * KP + tj * 4]), v1);
        }
    }
}

// =========================== Quad kernel ===========================
// grid = 32, block = 768 (24 warps = 8 b x 3 d). Kernel boundary = barrier.
__global__ void __launch_bounds__(QTHR, 1)
quad_kernel(const float* __restrict__ y_hat,
            const float* __restrict__ y,
            float* __restrict__ out) {
    __shared__ __align__(16) float S[GFLTS];     // full symmetric G
    __shared__ float w_s[8 * KP];
    __shared__ bool  s_last;

    const int tid = threadIdx.x;
    const int blk = blockIdx.x;

    // w build: 416 entries, single pass (768 threads).
    if (tid < 8 * KP) {
        int bl = tid / KP, k = tid - bl * KP;
        float wv = EPSF;
        if (k < KDIM) {
            int gi = (blk * 8 + bl) * KDIM + k;
            wv = __ldg(&y_hat[gi]) - __ldg(&y[gi]);
        }
        w_s[tid] = wv;
    }
    // Upper-tri G load: 2028 float4 over 768 threads (3 batched each).
    {
        float4 gv[3];
        int    gi[3];
#pragma unroll
        for (int i = 0; i < 3; i++) {
            int v = tid + i * QTHR;
            gi[i] = v;
            if (v < NPOS4)
                gv[i] = __ldcg(reinterpret_cast<const float4*>(g_G) + v);
        }
#pragma unroll
        for (int i = 0; i < 3; i++)
            if (gi[i] < NPOS4)
                reinterpret_cast<float4*>(S)[gi[i]] = gv[i];
    }
    __syncthreads();

    // Mirror-fill: S[d][k][j] = S[d][j][k] for k > j (lower tri was 0).
    // Upper-tri entries are only read, never written -> no hazard.
    for (int i = tid; i < GFLTS; i += QTHR) {
        int d = i / (KP * KP);
        int r = i - d * (KP * KP);
        int k = r / KP;
        int j = r - k * KP;
        if (k > j) S[i] = S[d * KP * KP + j * KP + k];
    }
    __syncthreads();

    // One warp per (b, d): 24 warps = 8 b x 3 d.
    const int wid  = tid >> 5;
    const int lane = tid & 31;
    const int bl   = wid / 3;        // 0..7
    const int d    = wid - bl * 3;   // 0..2

    const float* w  = w_s + bl * KP;
    const float* Gd = S + d * KP * KP;

    const int  k1   = lane;          // 0..31
    const int  k2v  = lane + 32;     // 32..63
    const bool has2 = (k2v < KP);    // lanes 0..19
    const int  k2   = has2 ? k2v : 0;

    const float wk1 = w[k1];
    const float wk2 = has2 ? w[k2v] : 0.0f;

    // t = (S w) at owned columns; pure LDS+FFMA, no selects.
    float t1 = 0.0f, t2 = 0.0f;
#pragma unroll 13
    for (int k = 0; k < KP; k++) {
        float wk = w[k];
        t1 += wk * Gd[k * KP + k1];
        t2 += wk * Gd[k * KP + k2];
    }
    float p = wk1 * t1 + wk2 * t2;   // w^T S w partial
#pragma unroll
    for (int o = 16; o > 0; o >>= 1)
        p += __shfl_down_sync(0xFFFFFFFFu, p, o);
    if (lane == 0) atomicAdd(&g_out, sqrtf(p));

    // Finisher: last quad block writes out and resets device state.
    __syncthreads();
    if (tid == 0) {
        __threadfence();
        unsigned old = atomicAdd(&g_ctr, 1u);
        s_last = (old == (unsigned)(QBLKS - 1));
    }
    __syncthreads();
    if (!s_last) return;

    if (tid == 0) {
        float v = atomicAdd(&g_out, 0.0f);
        out[0] = v * MULTF;
    }
    for (int i = tid; i < GFLTS; i += QTHR) g_G[i] = 0.0f;
    if (tid == 0) {
        g_out = 0.0f;
        g_ctr = 0u;
    }
}

extern "C" void kernel_launch(void* const* d_in, const int* in_sizes, int n_in,
                              void* d_out, int out_size) {
    const float* y_hat = (const float*)d_in[0];  // [256, 51]
    const float* y     = (const float*)d_in[1];  // [256, 51]
    // d_in[2] = face — cancels out of the loss, unused
    const float* bs    = (const float*)d_in[3];  // [51, 8192, 3]
    float* out = (float*)d_out;

    gram_kernel<<<GBLKS, NTHR>>>(bs);
    quad_kernel<<<QBLKS, QTHR>>>(y_hat, y, out);
}

// round 15
// speedup vs baseline: 1.0017x; 1.0017x over previous
#include <cuda_runtime.h>

// Fixed shapes
#define KDIM   51
#define KP     52                // padded K (row 51 = ones, carries EPS exactly)
#define BDIM   256
#define CCOLS  24576             // 8192 points * 3
#define TCOLS  192               // columns per gram block (64 per d)
#define GBLKS  128               // gram blocks (1/SM, all co-resident)
#define QBLKS  32                // blocks that continue into the quad phase
#define NTHR   288               // 9 warps; 273 combos -> <=1 per thread
#define COLS_D 64                // columns per d per block
#define CPAD   56                // padded k-extent (multiple of 4 for LDS.128)
#define NTILE  13                // 52/4 k-tiles
#define NPAIRT 91                // upper-tri tile pairs
#define NCOMBO 273               // 91 * 3 d
#define NV4    (KDIM * TCOLS / 4)  // 2448 float4 loads per block
#define NLOAD  9                   // ceil(2448 / 288)
#define GFLTS  (3 * KP * KP)       // 8112
#define NPOS4  (GFLTS / 4)         // 2028
#define EPSF   1e-6f
#define MULTF  0.0025f

// Self-resetting device state (zero-init at module load; finisher resets).
__device__ __align__(16) float g_G[GFLTS];   // FULL symmetric Gram
__device__ float    g_out;
__device__ unsigned g_ctr1;
__device__ unsigned g_ctr2;

typedef unsigned long long ull;

__device__ __forceinline__ ull pack2(float a, float b) {
    ull r; asm("mov.b64 %0, {%1, %2};" : "=l"(r) : "f"(a), "f"(b)); return r;
}
__device__ __forceinline__ void unpack2(ull v, float& a, float& b) {
    asm("mov.b64 {%0, %1}, %2;" : "=f"(a), "=f"(b) : "l"(v));
}
__device__ __forceinline__ void ffma2(ull& d, ull a, ull b) {
    asm("fma.rn.f32x2 %0, %1, %2, %0;" : "+l"(d) : "l"(a), "l"(b));
}

__global__ void __launch_bounds__(NTHR, 1)
fused_kernel(const float* __restrict__ bs,
             const float* __restrict__ y_hat,
             const float* __restrict__ y,
             float* __restrict__ out) {
    // Phase 1: As[3][COLS_D][CPAD] = 10752 floats (43008 B)
    // Phase 2 (same buffer): S_s (8112 floats) + w_s (416 floats)
    __shared__ __align__(16) float smem[3 * COLS_D * CPAD];
    __shared__ bool s_last;

    const int tid = threadIdx.x;
    const int blk = blockIdx.x;

    // ---- Prefetch w operands for quad blocks (latency hidden by phase 1) ----
    float wpre[2];
    int   widx[2];
    const bool is_quad = (blk < QBLKS);
#pragma unroll
    for (int j = 0; j < 2; j++) {
        int i = tid + j * NTHR;            // covers 0..575 >= 416
        widx[j] = i;
        wpre[j] = EPSF;
        if (is_quad && i < 8 * KP) {
            int bl = i / KP, k = i - bl * KP;
            if (k < KDIM) {
                int gi = (blk * 8 + bl) * KDIM + k;
                wpre[j] = __ldg(&y_hat[gi]) - __ldg(&y[gi]);
            }
        }
    }

    // ======================= Phase 1: Gram =======================
    {
        const int c0 = blk * TCOLS;
        // Front-batched loads: 9 independent LDG.128 per thread (MLP ~9).
        float4 vals[NLOAD];
        int    vv[NLOAD];
#pragma unroll
        for (int i = 0; i < NLOAD; i++) {
            int v = tid + i * NTHR;
            vv[i] = v;
            if (v < NV4) {
                int k = v / 48;            // 48 float4 per row
                int q = v - k * 48;
                vals[i] = *reinterpret_cast<const float4*>(
                    bs + (size_t)k * CCOLS + c0 + q * 4);
            }
        }
        // De-interleave stores: c = q*4 + j; d = c%3, col = c/3.
#pragma unroll
        for (int i = 0; i < NLOAD; i++) {
            if (vv[i] < NV4) {
                int k  = vv[i] / 48;
                int q  = vv[i] - k * 48;
                int c  = q * 4;
                int q3 = c % 3;
                int qc = c / 3;
                float x[4] = {vals[i].x, vals[i].y, vals[i].z, vals[i].w};
#pragma unroll
                for (int j = 0; j < 4; j++) {
                    int t   = q3 + j;              // 0..5
                    int add = (t >= 3) ? 1 : 0;
                    int d   = t - 3 * add;
                    int col = qc + add;
                    smem[(d * COLS_D + col) * CPAD + k] = x[j];
                }
            }
        }
        // Ones row (k = 51): carries EPS cross & square terms exactly.
        if (tid < TCOLS) {
            int d = tid % 3, col = tid / 3;
            smem[(d * COLS_D + col) * CPAD + KDIM] = 1.0f;
        }
        __syncthreads();

        // <=1 combo per thread, staggered across blocks (37 coprime to 273).
        if (tid < NCOMBO) {
            int combo = (tid + blk * 37) % NCOMBO;
            int d2   = combo / NPAIRT;
            int tile = combo - d2 * NPAIRT;
            int ti = 0, rem = tile;
            while (rem >= NTILE - ti) { rem -= NTILE - ti; ti++; }
            int tj = ti + rem;  // ti <= tj

            ull acc2[2][4];
#pragma unroll
            for (int p = 0; p < 2; p++)
#pragma unroll
                for (int s = 0; s < 4; s++) acc2[p][s] = 0ull;

            const float* base = smem + d2 * COLS_D * CPAD;
#pragma unroll 8
            for (int col2 = 0; col2 < COLS_D; col2++) {
                longlong2 a = *reinterpret_cast<const longlong2*>(
                    base + col2 * CPAD + ti * 4);
                float4 b = *reinterpret_cast<const float4*>(
                    base + col2 * CPAD + tj * 4);
                ull bx = pack2(b.x, b.x), by = pack2(b.y, b.y);
                ull bz = pack2(b.z, b.z), bw = pack2(b.w, b.w);
                ffma2(acc2[0][0], (ull)a.x, bx);
                ffma2(acc2[0][1], (ull)a.x, by);
                ffma2(acc2[0][2], (ull)a.x, bz);
                ffma2(acc2[0][3], (ull)a.x, bw);
                ffma2(acc2[1][0], (ull)a.y, bx);
                ffma2(acc2[1][1], (ull)a.y, by);
                ffma2(acc2[1][2], (ull)a.y, bz);
                ffma2(acc2[1][3], (ull)a.y, bw);
            }

            // Unpack full 4x4 tile: a4[r][s] = acc[r][s].
            float a4[4][4];
#pragma unroll
            for (int p = 0; p < 2; p++) {
#pragma unroll
                for (int s = 0; s < 4; s++) {
                    float lo, hi;
                    unpack2(acc2[p][s], lo, hi);
                    a4[2 * p][s]     = lo;
                    a4[2 * p + 1][s] = hi;
                }
            }
            float* Gd = &g_G[d2 * KP * KP];
            // Upper emission: rows 4ti+r, cols 4tj..4tj+3.
#pragma unroll
            for (int r = 0; r < 4; r++) {
                atomicAdd(reinterpret_cast<float4*>(
                              Gd + (ti * 4 + r) * KP + tj * 4),
                          make_float4(a4[r][0], a4[r][1], a4[r][2], a4[r][3]));
            }
            // Mirror emission (ti != tj): rows 4tj+s, cols 4ti..4ti+3.
            if (ti != tj) {
#pragma unroll
                for (int s = 0; s < 4; s++) {
                    atomicAdd(reinterpret_cast<float4*>(
                                  Gd + (tj * 4 + s) * KP + ti * 4),
                              make_float4(a4[0][s], a4[1][s],
                                          a4[2][s], a4[3][s]));
                }
            }
        }
    }
    __syncthreads();   // all LDS of As done -> safe to repurpose smem
    if (tid == 0) {
        __threadfence();
        atomicAdd(&g_ctr1, 1u);
    }

    if (!is_quad) return;

    // Stash prefetched w into the w_s slot while the barrier is pending.
    float* S_s = smem;                 // 8112 floats (full symmetric)
    float* w_s = smem + GFLTS;         // 416 floats
#pragma unroll
    for (int j = 0; j < 2; j++)
        if (widx[j] < 8 * KP) w_s[widx[j]] = wpre[j];

    // Grid-wide barrier: all 128 gram blocks are co-resident (1/SM).
    if (tid == 0) {
        while (atomicAdd(&g_ctr1, 0u) < (unsigned)GBLKS) { }
    }
    __syncthreads();

    // ======================= Phase 2: Quad =======================
    // Batched vector reload of S (8x float4 per thread, MLP 8).
    {
        float4 gv[8];
        int    gi[8];
#pragma unroll
        for (int i = 0; i < 8; i++) {
            int v = tid + i * NTHR;
            gi[i] = v;
            if (v < NPOS4)
                gv[i] = __ldcg(reinterpret_cast<const float4*>(g_G) + v);
        }
#pragma unroll
        for (int i = 0; i < 8; i++)
            if (gi[i] < NPOS4)
                reinterpret_cast<float4*>(S_s)[gi[i]] = gv[i];
    }
    __syncthreads();

    const int wid  = tid >> 5;
    const int lane = tid & 31;

    if (wid < 8) {
        const int  k1   = lane;
        const int  k2v  = lane + 32;
        const bool has2 = (k2v < KP);
        const int  k2   = has2 ? k2v : 0;

        const float* w = w_s + wid * KP;
        const float wk1 = w[k1];
        const float wk2 = has2 ? w[k2v] : 0.0f;

        float total = 0.0f;
#pragma unroll 1
        for (int d = 0; d < 3; d++) {
            const float* S = S_s + d * KP * KP;
            float t1 = 0.0f, t2 = 0.0f;
#pragma unroll 13
            for (int k = 0; k < KP; k++) {
                float wk = w[k];
                t1 += wk * S[k * KP + k1];
                t2 += wk * S[k * KP + k2];
            }
            float p = wk1 * t1 + wk2 * t2;   // w^T S w (S symmetric, no x2)
#pragma unroll
            for (int o = 16; o > 0; o >>= 1)
                p += __shfl_down_sync(0xFFFFFFFFu, p, o);
            if (lane == 0) total += sqrtf(p);
        }
        if (lane == 0) atomicAdd(&g_out, total);
    }

    // ======================= Finisher =======================
    __syncthreads();
    if (tid == 0) {
        __threadfence();
        unsigned old = atomicAdd(&g_ctr2, 1u);
        s_last = (old == (unsigned)(QBLKS - 1));
    }
    __syncthreads();
    if (!s_last) return;

    if (tid == 0) {
        float v = atomicAdd(&g_out, 0.0f);
        out[0] = v * MULTF;
    }
    for (int i = tid; i < GFLTS; i += NTHR) g_G[i] = 0.0f;
    if (tid == 0) {
        g_out  = 0.0f;
        g_ctr1 = 0u;
        g_ctr2 = 0u;
    }
}

extern "C" void kernel_launch(void* const* d_in, const int* in_sizes, int n_in,
                              void* d_out, int out_size) {
    const float* y_hat = (const float*)d_in[0];  // [256, 51]
    const float* y     = (const float*)d_in[1];  // [256, 51]
    // d_in[2] = face — cancels out of the loss, unused
    const float* bs    = (const float*)d_in[3];  // [51, 8192, 3]
    float* out = (float*)d_out;

    fused_kernel<<<GBLKS, NTHR>>>(bs, y_hat, y, out);
}

// round 16
// speedup vs baseline: 1.1364x; 1.1345x over previous
#include <cuda_runtime.h>

// Fixed shapes
#define KDIM   51
#define KP     52                // padded K (row 51 = ones, carries EPS exactly)
#define BDIM   256
#define CCOLS  24576             // 8192 points * 3
#define TCOLS  192               // columns per gram block (64 per d)
#define GBLKS  128               // gram blocks (1/SM, all co-resident)
#define NTHR   288               // 9 warps; 273 combos -> <=1 per thread
#define COLS_D 64                // columns per d per block
#define CPAD   56                // padded k-extent (multiple of 4 for LDS.128)
#define NTILE  13                // 52/4 k-tiles
#define NPAIRT 91                // upper-tri tile pairs
#define NCOMBO 273               // 91 * 3 d
#define NV4    (KDIM * TCOLS / 4)  // 2448 float4 loads per block
#define NLOAD  9                   // ceil(2448 / 288)
#define GFLTS  (3 * KP * KP)       // 8112
#define NPOS4  (GFLTS / 4)         // 2028
#define BPB    2                   // batch rows per block in quad (256/128)
#define EPSF   1e-6f
#define MULTF  0.0025f

// Self-resetting device state (zero-init at module load; finisher resets).
__device__ __align__(16) float g_G[GFLTS];   // upper-tri Gram
__device__ float    g_out;
__device__ unsigned g_ctr1;
__device__ unsigned g_ctr2;

typedef unsigned long long ull;

__device__ __forceinline__ ull pack2(float a, float b) {
    ull r; asm("mov.b64 %0, {%1, %2};" : "=l"(r) : "f"(a), "f"(b)); return r;
}
__device__ __forceinline__ void unpack2(ull v, float& a, float& b) {
    asm("mov.b64 {%0, %1}, %2;" : "=f"(a), "=f"(b) : "l"(v));
}
__device__ __forceinline__ void ffma2(ull& d, ull a, ull b) {
    asm("fma.rn.f32x2 %0, %1, %2, %0;" : "+l"(d) : "l"(a), "l"(b));
}

__global__ void __launch_bounds__(NTHR, 1)
fused_kernel(const float* __restrict__ bs,
             const float* __restrict__ y_hat,
             const float* __restrict__ y,
             float* __restrict__ out) {
    // Phase 1: As[3][COLS_D][CPAD] = 10752 floats (43008 B)
    // Phase 2 (same buffer): G_s (8112 floats) + w_s (104 floats)
    __shared__ __align__(16) float smem[3 * COLS_D * CPAD];
    __shared__ bool s_last;

    const int tid = threadIdx.x;
    const int blk = blockIdx.x;

    // ---- Prefetch w operands (2 batch rows per block; 104 entries) ----
    float wpre = EPSF;
    if (tid < BPB * KP) {
        int bl = tid / KP, k = tid - bl * KP;
        if (k < KDIM) {
            int gi = (blk * BPB + bl) * KDIM + k;
            wpre = __ldg(&y_hat[gi]) - __ldg(&y[gi]);
        }
    }

    // ======================= Phase 1: Gram (r8-identical) =======================
    {
        const int c0 = blk * TCOLS;
        // Front-batched loads: 9 independent LDG.128 per thread (MLP ~9).
        float4 vals[NLOAD];
        int    vv[NLOAD];
#pragma unroll
        for (int i = 0; i < NLOAD; i++) {
            int v = tid + i * NTHR;
            vv[i] = v;
            if (v < NV4) {
                int k = v / 48;            // 48 float4 per row
                int q = v - k * 48;
                vals[i] = *reinterpret_cast<const float4*>(
                    bs + (size_t)k * CCOLS + c0 + q * 4);
            }
        }
        // De-interleave stores: c = q*4 + j; d = c%3, col = c/3.
#pragma unroll
        for (int i = 0; i < NLOAD; i++) {
            if (vv[i] < NV4) {
                int k  = vv[i] / 48;
                int q  = vv[i] - k * 48;
                int c  = q * 4;
                int q3 = c % 3;
                int qc = c / 3;
                float x[4] = {vals[i].x, vals[i].y, vals[i].z, vals[i].w};
#pragma unroll
                for (int j = 0; j < 4; j++) {
                    int t   = q3 + j;              // 0..5
                    int add = (t >= 3) ? 1 : 0;
                    int d   = t - 3 * add;
                    int col = qc + add;
                    smem[(d * COLS_D + col) * CPAD + k] = x[j];
                }
            }
        }
        // Ones row (k = 51): carries EPS cross & square terms exactly.
        if (tid < TCOLS) {
            int d = tid % 3, col = tid / 3;
            smem[(d * COLS_D + col) * CPAD + KDIM] = 1.0f;
        }
        __syncthreads();

        // <=1 combo per thread, staggered across blocks (37 coprime to 273).
        if (tid < NCOMBO) {
            int combo = (tid + blk * 37) % NCOMBO;
            int d2   = combo / NPAIRT;
            int tile = combo - d2 * NPAIRT;
            int ti = 0, rem = tile;
            while (rem >= NTILE - ti) { rem -= NTILE - ti; ti++; }
            int tj = ti + rem;  // ti <= tj

            ull acc2[2][4];
#pragma unroll
            for (int p = 0; p < 2; p++)
#pragma unroll
                for (int s = 0; s < 4; s++) acc2[p][s] = 0ull;

            const float* base = smem + d2 * COLS_D * CPAD;
#pragma unroll 8
            for (int col2 = 0; col2 < COLS_D; col2++) {
                longlong2 a = *reinterpret_cast<const longlong2*>(
                    base + col2 * CPAD + ti * 4);
                float4 b = *reinterpret_cast<const float4*>(
                    base + col2 * CPAD + tj * 4);
                ull bx = pack2(b.x, b.x), by = pack2(b.y, b.y);
                ull bz = pack2(b.z, b.z), bw = pack2(b.w, b.w);
                ffma2(acc2[0][0], (ull)a.x, bx);
                ffma2(acc2[0][1], (ull)a.x, by);
                ffma2(acc2[0][2], (ull)a.x, bz);
                ffma2(acc2[0][3], (ull)a.x, bw);
                ffma2(acc2[1][0], (ull)a.y, bx);
                ffma2(acc2[1][1], (ull)a.y, by);
                ffma2(acc2[1][2], (ull)a.y, bz);
                ffma2(acc2[1][3], (ull)a.y, bw);
            }

#pragma unroll
            for (int p = 0; p < 2; p++) {
                float r0x, r1x, r0y, r1y, r0z, r1z, r0w, r1w;
                unpack2(acc2[p][0], r0x, r1x);
                unpack2(acc2[p][1], r0y, r1y);
                unpack2(acc2[p][2], r0z, r1z);
                unpack2(acc2[p][3], r0w, r1w);
                float4 v0 = make_float4(r0x, r0y, r0z, r0w);
                float4 v1 = make_float4(r1x, r1y, r1z, r1w);
                int r0 = ti * 4 + 2 * p;
                atomicAdd(reinterpret_cast<float4*>(
                              &g_G[d2 * KP * KP + r0 * KP + tj * 4]), v0);
                atomicAdd(reinterpret_cast<float4*>(
                              &g_G[d2 * KP * KP + (r0 + 1) * KP + tj * 4]), v1);
            }
        }
    }
    __syncthreads();   // all LDS of As done -> safe to repurpose smem

    // Stash prefetched w; then grid barrier. EVERY block continues to quad.
    float* G_s = smem;                 // 8112 floats (upper-tri)
    float* w_s = smem + GFLTS;         // 104 floats
    if (tid < BPB * KP) w_s[tid] = wpre;

    if (tid == 0) {
        __threadfence();
        atomicAdd(&g_ctr1, 1u);
        while (atomicAdd(&g_ctr1, 0u) < (unsigned)GBLKS) { }
    }
    __syncthreads();

    // ============ Phase 2: Quad, distributed over all 128 blocks ============
    // Batched vector reload of G (8x float4 per thread, MLP 8).
    {
        float4 gv[8];
        int    gi[8];
#pragma unroll
        for (int i = 0; i < 8; i++) {
            int v = tid + i * NTHR;
            gi[i] = v;
            if (v < NPOS4)
                gv[i] = __ldcg(reinterpret_cast<const float4*>(g_G) + v);
        }
#pragma unroll
        for (int i = 0; i < 8; i++)
            if (gi[i] < NPOS4)
                reinterpret_cast<float4*>(G_s)[gi[i]] = gv[i];
    }
    __syncthreads();

    const int wid  = tid >> 5;
    const int lane = tid & 31;

    // 6 warps: warp w -> (bl = w/3, d = w%3). Warps 6-8 idle.
    if (wid < BPB * 3) {
        const int bl = wid / 3;
        const int d  = wid - bl * 3;

        const int  k1   = lane;
        const int  k2v  = lane + 32;
        const bool has2 = (k2v < KP);
        const int  k2   = has2 ? k2v : KDIM;

        const float* w = w_s + bl * KP;
        const float wk1 = w[k1];
        const float wk2 = has2 ? w[k2v] : 0.0f;

        const float* G = G_s + d * KP * KP;
        float t1 = 0.0f, t2 = 0.0f;
#pragma unroll 13
        for (int k = 0; k < KP; k++) {
            float wk = w[k];
            float g1 = G[k * KP + k1];
            float g2 = G[k * KP + k2];
            float f1 = (k < k1)  ? wk : ((k == k1)  ? 0.5f * wk : 0.0f);
            float f2 = (k < k2v) ? wk : ((k == k2v) ? 0.5f * wk : 0.0f);
            t1 += g1 * f1;
            t2 += g2 * f2;
        }
        float p = 2.0f * (wk1 * t1 + wk2 * t2);
#pragma unroll
        for (int o = 16; o > 0; o >>= 1)
            p += __shfl_down_sync(0xFFFFFFFFu, p, o);
        if (lane == 0) atomicAdd(&g_out, sqrtf(p));
    }

    // ======================= Finisher (last of 128) =======================
    __syncthreads();
    if (tid == 0) {
        __threadfence();
        unsigned old = atomicAdd(&g_ctr2, 1u);
        s_last = (old == (unsigned)(GBLKS - 1));
    }
    __syncthreads();
    if (!s_last) return;

    if (tid == 0) {
        float v = atomicAdd(&g_out, 0.0f);
        out[0] = v * MULTF;
    }
    for (int i = tid; i < GFLTS; i += NTHR) g_G[i] = 0.0f;
    if (tid == 0) {
        g_out  = 0.0f;
        g_ctr1 = 0u;
        g_ctr2 = 0u;
    }
}

extern "C" void kernel_launch(void* const* d_in, const int* in_sizes, int n_in,
                              void* d_out, int out_size) {
    const float* y_hat = (const float*)d_in[0];  // [256, 51]
    const float* y     = (const float*)d_in[1];  // [256, 51]
    // d_in[2] = face — cancels out of the loss, unused
    const float* bs    = (const float*)d_in[3];  // [51, 8192, 3]
    float* out = (float*)d_out;

    fused_kernel<<<GBLKS, NTHR>>>(bs, y_hat, y, out);
}

// round 17
// speedup vs baseline: 1.2739x; 1.1210x over previous
#include <cuda_runtime.h>

// Fixed shapes
#define KDIM   51
#define KP     52                // padded K (row 51 = ones, carries EPS exactly)
#define BDIM   256
#define CCOLS  24576             // 8192 points * 3
#define TCOLS  192               // columns per gram block (64 per d)
#define GBLKS  128               // gram blocks (1/SM, all co-resident)
#define NTHR   288               // 9 warps; 273 combos -> <=1 per thread
#define COLS_D 64                // columns per d per block
#define CPAD   60                // padded k-extent; 60*4=240B (16B-aligned),
                                 // bank stride 28 -> 4-way STS conflicts (vs 8 at 56)
#define NTILE  13                // 52/4 k-tiles
#define NPAIRT 91                // upper-tri tile pairs
#define NCOMBO 273               // 91 * 3 d
#define NV4    (KDIM * TCOLS / 4)  // 2448 float4 loads per block
#define NLOAD  9                   // ceil(2448 / 288)
#define GFLTS  (3 * KP * KP)       // 8112
#define NPOS4  (GFLTS / 4)         // 2028
#define BPB    2                   // batch rows per block in quad (256/128)
#define EPSF   1e-6f
#define MULTF  0.0025f

// Self-resetting device state (zero-init at module load; finisher resets).
__device__ __align__(16) float g_G[GFLTS];   // upper-tri Gram
__device__ float    g_out;
__device__ unsigned g_ctr1;
__device__ unsigned g_ctr2;

typedef unsigned long long ull;

__device__ __forceinline__ ull pack2(float a, float b) {
    ull r; asm("mov.b64 %0, {%1, %2};" : "=l"(r) : "f"(a), "f"(b)); return r;
}
__device__ __forceinline__ void unpack2(ull v, float& a, float& b) {
    asm("mov.b64 {%0, %1}, %2;" : "=f"(a), "=f"(b) : "l"(v));
}
__device__ __forceinline__ void ffma2(ull& d, ull a, ull b) {
    asm("fma.rn.f32x2 %0, %1, %2, %0;" : "+l"(d) : "l"(a), "l"(b));
}

__global__ void __launch_bounds__(NTHR, 1)
fused_kernel(const float* __restrict__ bs,
             const float* __restrict__ y_hat,
             const float* __restrict__ y,
             float* __restrict__ out) {
    // Phase 1: As[3][COLS_D][CPAD] = 11520 floats (46080 B)
    // Phase 2 (same buffer): G_s (8112 floats) + w_s (104 floats)
    __shared__ __align__(16) float smem[3 * COLS_D * CPAD];
    __shared__ bool s_last;

    const int tid = threadIdx.x;
    const int blk = blockIdx.x;

    // ---- Prefetch w operands (2 batch rows per block; 104 entries) ----
    float wpre = EPSF;
    if (tid < BPB * KP) {
        int bl = tid / KP, k = tid - bl * KP;
        if (k < KDIM) {
            int gi = (blk * BPB + bl) * KDIM + k;
            wpre = __ldg(&y_hat[gi]) - __ldg(&y[gi]);
        }
    }

    // ======================= Phase 1: Gram =======================
    {
        const int c0 = blk * TCOLS;
        // Front-batched loads: 9 independent LDG.128 per thread (MLP ~9).
        float4 vals[NLOAD];
        int    vv[NLOAD];
#pragma unroll
        for (int i = 0; i < NLOAD; i++) {
            int v = tid + i * NTHR;
            vv[i] = v;
            if (v < NV4) {
                int k = v / 48;            // 48 float4 per row
                int q = v - k * 48;
                vals[i] = *reinterpret_cast<const float4*>(
                    bs + (size_t)k * CCOLS + c0 + q * 4);
            }
        }
        // De-interleave stores: c = q*4 + j; d = c%3, col = c/3.
#pragma unroll
        for (int i = 0; i < NLOAD; i++) {
            if (vv[i] < NV4) {
                int k  = vv[i] / 48;
                int q  = vv[i] - k * 48;
                int c  = q * 4;
                int q3 = c % 3;
                int qc = c / 3;
                float x[4] = {vals[i].x, vals[i].y, vals[i].z, vals[i].w};
#pragma unroll
                for (int j = 0; j < 4; j++) {
                    int t   = q3 + j;              // 0..5
                    int add = (t >= 3) ? 1 : 0;
                    int d   = t - 3 * add;
                    int col = qc + add;
                    smem[(d * COLS_D + col) * CPAD + k] = x[j];
                }
            }
        }
        // Ones row (k = 51): carries EPS cross & square terms exactly.
        if (tid < TCOLS) {
            int d = tid % 3, col = tid / 3;
            smem[(d * COLS_D + col) * CPAD + KDIM] = 1.0f;
        }
        __syncthreads();

        // <=1 combo per thread, staggered across blocks (37 coprime to 273).
        if (tid < NCOMBO) {
            int combo = (tid + blk * 37) % NCOMBO;
            int d2   = combo / NPAIRT;
            int tile = combo - d2 * NPAIRT;
            int ti = 0, rem = tile;
            while (rem >= NTILE - ti) { rem -= NTILE - ti; ti++; }
            int tj = ti + rem;  // ti <= tj

            // acc2[p][v]: p = row-pair {01,23}; v = {B01, B10, B23, B32}
            ull acc2[2][4];
#pragma unroll
            for (int p = 0; p < 2; p++)
#pragma unroll
                for (int s = 0; s < 4; s++) acc2[p][s] = 0ull;

            const float* base = smem + d2 * COLS_D * CPAD;
#pragma unroll 8
            for (int col2 = 0; col2 < COLS_D; col2++) {
                // a: 2 natural packed pairs (LDS.128)
                longlong2 qa = *reinterpret_cast<const longlong2*>(
                    base + col2 * CPAD + ti * 4);
                // b: 2 natural packed pairs (LDS.128) — no duplication MOVs
                longlong2 qb = *reinterpret_cast<const longlong2*>(
                    base + col2 * CPAD + tj * 4);
                ull B01 = (ull)qb.x, B23 = (ull)qb.y;
                float b0, b1, b2, b3;
                unpack2(B01, b0, b1);
                unpack2(B23, b2, b3);
                ull B10 = pack2(b1, b0);    // swap: 2 MOVs total/iter (vs 8)
                ull B32 = pack2(b3, b2);

                ffma2(acc2[0][0], (ull)qa.x, B01);
                ffma2(acc2[0][1], (ull)qa.x, B10);
                ffma2(acc2[0][2], (ull)qa.x, B23);
                ffma2(acc2[0][3], (ull)qa.x, B32);
                ffma2(acc2[1][0], (ull)qa.y, B01);
                ffma2(acc2[1][1], (ull)qa.y, B10);
                ffma2(acc2[1][2], (ull)qa.y, B23);
                ffma2(acc2[1][3], (ull)qa.y, B32);
            }

            // Emission. acc2[p][0]=(a_{2p}b0, a_{2p+1}b1), [1]=(a_{2p}b1, a_{2p+1}b0),
            //           [2]=(a_{2p}b2, a_{2p+1}b3), [3]=(a_{2p}b3, a_{2p+1}b2).
            // Row 4ti+2p   = (d0.lo, d1.lo, d2.lo, d3.lo)
            // Row 4ti+2p+1 = (d1.hi, d0.hi, d3.hi, d2.hi)
#pragma unroll
            for (int p = 0; p < 2; p++) {
                float d0l, d0h, d1l, d1h, d2l, d2h, d3l, d3h;
                unpack2(acc2[p][0], d0l, d0h);
                unpack2(acc2[p][1], d1l, d1h);
                unpack2(acc2[p][2], d2l, d2h);
                unpack2(acc2[p][3], d3l, d3h);
                float4 v0 = make_float4(d0l, d1l, d2l, d3l);
                float4 v1 = make_float4(d1h, d0h, d3h, d2h);
                int r0 = ti * 4 + 2 * p;
                atomicAdd(reinterpret_cast<float4*>(
                              &g_G[d2 * KP * KP + r0 * KP + tj * 4]), v0);
                atomicAdd(reinterpret_cast<float4*>(
                              &g_G[d2 * KP * KP + (r0 + 1) * KP + tj * 4]), v1);
            }
        }
    }
    __syncthreads();   // all LDS of As done -> safe to repurpose smem

    // Stash prefetched w; then grid barrier. EVERY block continues to quad.
    float* G_s = smem;                 // 8112 floats (upper-tri)
    float* w_s = smem + GFLTS;         // 104 floats
    if (tid < BPB * KP) w_s[tid] = wpre;

    if (tid == 0) {
        __threadfence();
        atomicAdd(&g_ctr1, 1u);
        while (atomicAdd(&g_ctr1, 0u) < (unsigned)GBLKS) { }
    }
    __syncthreads();

    // ============ Phase 2: Quad, distributed over all 128 blocks ============
    // Batched vector reload of G (8x float4 per thread, MLP 8).
    {
        float4 gv[8];
        int    gi[8];
#pragma unroll
        for (int i = 0; i < 8; i++) {
            int v = tid + i * NTHR;
            gi[i] = v;
            if (v < NPOS4)
                gv[i] = __ldcg(reinterpret_cast<const float4*>(g_G) + v);
        }
#pragma unroll
        for (int i = 0; i < 8; i++)
            if (gi[i] < NPOS4)
                reinterpret_cast<float4*>(G_s)[gi[i]] = gv[i];
    }
    __syncthreads();

    const int wid  = tid >> 5;
    const int lane = tid & 31;

    // 6 warps: warp w -> (bl = w/3, d = w%3). Warps 6-8 idle.
    if (wid < BPB * 3) {
        const int bl = wid / 3;
        const int d  = wid - bl * 3;

        const int  k1   = lane;
        const int  k2v  = lane + 32;
        const bool has2 = (k2v < KP);
        const int  k2   = has2 ? k2v : KDIM;

        const float* w = w_s + bl * KP;
        const float wk1 = w[k1];
        const float wk2 = has2 ? w[k2v] : 0.0f;

        const float* G = G_s + d * KP * KP;
        float t1 = 0.0f, t2 = 0.0f;
#pragma unroll 13
        for (int k = 0; k < KP; k++) {
            float wk = w[k];
            float g1 = G[k * KP + k1];
            float g2 = G[k * KP + k2];
            float f1 = (k < k1)  ? wk : ((k == k1)  ? 0.5f * wk : 0.0f);
            float f2 = (k < k2v) ? wk : ((k == k2v) ? 0.5f * wk : 0.0f);
            t1 += g1 * f1;
            t2 += g2 * f2;
        }
        float p = 2.0f * (wk1 * t1 + wk2 * t2);
#pragma unroll
        for (int o = 16; o > 0; o >>= 1)
            p += __shfl_down_sync(0xFFFFFFFFu, p, o);
        if (lane == 0) atomicAdd(&g_out, sqrtf(p));
    }

    // ======================= Finisher (last of 128) =======================
    __syncthreads();
    if (tid == 0) {
        __threadfence();
        unsigned old = atomicAdd(&g_ctr2, 1u);
        s_last = (old == (unsigned)(GBLKS - 1));
    }
    __syncthreads();
    if (!s_last) return;

    if (tid == 0) {
        float v = atomicAdd(&g_out, 0.0f);
        out[0] = v * MULTF;
    }
    for (int i = tid; i < GFLTS; i += NTHR) g_G[i] = 0.0f;
    if (tid == 0) {
        g_out  = 0.0f;
        g_ctr1 = 0u;
        g_ctr2 = 0u;
    }
}

extern "C" void kernel_launch(void* const* d_in, const int* in_sizes, int n_in,
                              void* d_out, int out_size) {
    const float* y_hat = (const float*)d_in[0];  // [256, 51]
    const float* y     = (const float*)d_in[1];  // [256, 51]
    // d_in[2] = face — cancels out of the loss, unused
    const float* bs    = (const float*)d_in[3];  // [51, 8192, 3]
    float* out = (float*)d_out;

    fused_kernel<<<GBLKS, NTHR>>>(bs, y_hat, y, out);
}